// round 16
// baseline (speedup 1.0000x reference)
#include <cuda_runtime.h>
#include <cuda_bf16.h>
#include <cstdint>

#define BB 32
#define EE 256
#define TT 512
#define MM 8
#define NN 5
#define CC 512
#define RR 64
#define MNP 40
#define LN_EPS 1e-5f
#define INV_SCALE 0.044194173824159216f  /* 1/sqrt(512) */
#define FG 256   /* fused kernel grid (2 CTAs/SM, all co-resident) */

typedef unsigned long long u64;

__device__ __forceinline__ void fma2(u64& d, u64 a, u64 b){
    asm("fma.rn.f32x2 %0,%1,%2,%0;" : "+l"(d) : "l"(a), "l"(b));
}
__device__ __forceinline__ u64 dup2(float x){ u64 r; asm("mov.b64 %0,{%1,%1};":"=l"(r):"f"(x)); return r; }
__device__ __forceinline__ void un2(u64 v, float& lo, float& hi){ asm("mov.b64 {%0,%1},%2;":"=f"(lo),"=f"(hi):"l"(v)); }

__device__ __forceinline__ uint32_t smem_u32(const void* p) {
    uint32_t a;
    asm("{ .reg .u64 t; cvta.to.shared.u64 t, %1; cvt.u32.u64 %0, t; }" : "=r"(a) : "l"(p));
    return a;
}
#define CP16(dst, src) asm volatile("cp.async.cg.shared.global [%0], [%1], 16;" :: "r"(dst), "l"(src))
#define CP4(dst, src)  asm volatile("cp.async.ca.shared.global [%0], [%1], 4;" :: "r"(dst), "l"(src))
#define CP4Z(dst, src, sz) asm volatile("cp.async.ca.shared.global [%0], [%1], 4, %2;" :: "r"(dst), "l"(src), "r"(sz))
#define CP_COMMIT() asm volatile("cp.async.commit_group;" ::: "memory")
#define CP_WAIT2() asm volatile("cp.async.wait_group 2;" ::: "memory")
#define CP_WAIT1() asm volatile("cp.async.wait_group 1;" ::: "memory")
#define CP_WAIT0() asm volatile("cp.async.wait_group 0;" ::: "memory")

__device__ __forceinline__ void ldm_x4(uint32_t& r0, uint32_t& r1, uint32_t& r2, uint32_t& r3, uint32_t addr) {
    asm volatile("ldmatrix.sync.aligned.m8n8.x4.shared.b16 {%0,%1,%2,%3}, [%4];"
                 : "=r"(r0), "=r"(r1), "=r"(r2), "=r"(r3) : "r"(addr));
}
__device__ __forceinline__ void mma_bf16(float* d, const uint32_t* a, const uint32_t* b) {
    asm volatile("mma.sync.aligned.m16n8k16.row.col.f32.bf16.bf16.f32 "
                 "{%0,%1,%2,%3}, {%4,%5,%6,%7}, {%8,%9}, {%0,%1,%2,%3};"
                 : "+f"(d[0]), "+f"(d[1]), "+f"(d[2]), "+f"(d[3])
                 : "r"(a[0]), "r"(a[1]), "r"(a[2]), "r"(a[3]), "r"(b[0]), "r"(b[1]));
}

// ---------------- scratch (device globals; no allocation) ----------------
__device__ __nv_bfloat16 g_Zhi[BB*TT*CC], g_Zlo[BB*TT*CC];
__device__ __nv_bfloat16 g_Xhi[BB*TT*CC], g_Xlo[BB*TT*CC];
__device__ __nv_bfloat16 g_Bhi[CC*1024], g_Blo[CC*1024];
__device__ float g_Sxp[BB*32*CC];
__device__ float g_Pp[MNP*8*CC];
__device__ float g_Sx[BB*CC], g_X0[BB*CC], g_XT[BB*CC];
__device__ float g_Sp[MNP*CC], g_P0[MNP*CC], g_PT[MNP*CC];
__device__ float g_xq[BB*CC], g_pk[MNP*CC];
__device__ float g_qprot[BB*CC], g_keysp[MNP*CC], g_q[BB*CC];
__device__ float g_aw1[BB*MM*NN];      // RAW scaled dots (never overwritten)
__device__ float g_aw1s[BB*MM*NN];     // softmaxed
__device__ float g_SPm[BB*MM*CC], g_P0m[BB*MM*CC], g_PTm[BB*MM*CC];
__device__ float g_Sy[BB*MM*CC], g_Fy[BB*MM*CC], g_Ly[BB*MM*CC];
__device__ float g_yks[BB*MM*CC], g_k[BB*MM*CC];
__device__ float g_wcoef[BB*MNP];
__device__ __align__(256) float g_tmpW[CC*CC];
__device__ __align__(256) float g_Wz[CC*CC];
__device__ float g_bvw[CC], g_bz[CC];
__device__ float g_wsC[CC*RR], g_w0C[CC*RR], g_w2C[CC*RR];
__device__ float g_maskf[MNP];
__device__ float g_vp1[8*CC], g_vp2[8*CC];
__device__ float g_sc2[BB*MM];
__device__ unsigned g_leafc[32*32];    // padded leaf counters
__device__ unsigned g_rootc = 0, g_bargen = 0;

// ---------------- fused smem layouts (all alias one dynamic buffer) ----------------
struct GemmSm  { float sA[3][32][18]; float sW[3][32][128]; };
struct Gemm64Sm{ float sA[3][32][18]; float sW[3][32][64]; };
struct Gemm3Sm { float sA[3][3][32][18]; float sW[3][32][64]; };
struct PoolSm  { float sS[4][CC]; float sF[4][CC]; float sL[4][CC]; float smc[4][RR]; };
struct WprepSm { float t[64][65]; };
struct ZmixSm  { float sP[MNP][128]; float swc[32][41]; };
struct LnSm    { float sx[EE][33]; float smu[16]; float srs[16]; };
union FusedSm { GemmSm g; Gemm64Sm g64; Gemm3Sm g3; PoolSm p; WprepSm w; ZmixSm z; LnSm l; };

#define ASTRIDE 72
#define TILE_BYTES (128*ASTRIDE*2)     /* 18432 */
#define DSM_BYTES (6*TILE_BYTES)       /* 110592: [3]A + [3]B mma buffers; FusedSm aliases */
#define NSTAGE 48

__device__ __forceinline__ void gbar(unsigned& tgt) {
    __threadfence();
    __syncthreads();
    if (threadIdx.x == 0) {
        int leaf = blockIdx.x & 31;
        unsigned old = atomicInc(&g_leafc[leaf*32], FG/32 - 1);
        if (old == FG/32 - 1) {
            unsigned r = atomicInc(&g_rootc, 31);
            if (r == 31) atomicAdd(&g_bargen, 1);
        }
        while ((int)(*(volatile unsigned*)&g_bargen - tgt) < 0) __nanosleep(64);
    }
    tgt++;
    __syncthreads();
    __threadfence();
}

// ---------------- LayerNorm tile -> bf16 hi/lo + partial T-sums ----------------
__device__ void dev_ln(const float* __restrict__ x_ri,
                       const float* __restrict__ gam, const float* __restrict__ bet,
                       int b, int tblk, LnSm& s) {
    int t0 = tblk * 16;
    int tid = threadIdx.x;
    #pragma unroll
    for (int i = 0; i < 8; i++) {
        int id = tid + i*256;
        int e = id >> 3, q = id & 7;
        float4 v = *(const float4*)(x_ri + (size_t)(b*EE + e)*TT*2 + t0*2 + q*4);
        s.sx[e][q*4+0] = v.x; s.sx[e][q*4+1] = v.y; s.sx[e][q*4+2] = v.z; s.sx[e][q*4+3] = v.w;
    }
    __syncthreads();
    int w = tid >> 5, l = tid & 31;
    #pragma unroll
    for (int ttl = 0; ttl < 2; ttl++) {
        int tt = w*2 + ttl;
        float sv = 0.f, s2 = 0.f;
        #pragma unroll
        for (int i = 0; i < 8; i++) {
            int e = i*32 + l;
            float v0 = s.sx[e][tt*2], v1 = s.sx[e][tt*2+1];
            sv += v0 + v1; s2 += v0*v0 + v1*v1;
        }
        #pragma unroll
        for (int o = 16; o; o >>= 1) { sv += __shfl_down_sync(0xffffffffu, sv, o); s2 += __shfl_down_sync(0xffffffffu, s2, o); }
        if (l == 0) {
            float mu = sv * (1.f/CC);
            float var = s2 * (1.f/CC) - mu*mu;
            s.smu[tt] = mu; s.srs[tt] = rsqrtf(var + LN_EPS);
        }
    }
    __syncthreads();
    #pragma unroll
    for (int ci = 0; ci < 2; ci++) {
        int c = tid + ci*256;
        float gm = __ldg(&gam[c]), bt = __ldg(&bet[c]);
        int e = c >> 1, j = c & 1;
        float acc = 0.f;
        #pragma unroll
        for (int tt = 0; tt < 16; tt++) {
            float v = (s.sx[e][tt*2+j] - s.smu[tt]) * s.srs[tt] * gm + bt;
            acc += v;
            size_t row = (size_t)(b*TT + t0 + tt);
            __nv_bfloat16 h = __float2bfloat16(v);
            g_Xhi[row*CC + c] = h;
            g_Xlo[row*CC + c] = __float2bfloat16(v - __bfloat162float(h));
            if (tblk == 0 && tt == 0)  g_X0[b*CC + c] = v;
            if (tblk == 31 && tt == 15) g_XT[b*CC + c] = v;
        }
        g_Sxp[(size_t)(b*32 + tblk)*CC + c] = acc;
    }
    __syncthreads();
}

// 16 rows x 128 cols, 3-buffer cp.async pipeline, f32x2 accumulate
__device__ void dev_gemm(const float* __restrict__ A, const float* __restrict__ W,
                         const float* __restrict__ bias, float bscale,
                         float* __restrict__ C, int rows, int row0, int col0, GemmSm& s) {
    int tid = threadIdx.x;
    int c = tid & 127, rg = tid >> 7;
    u64 acc2[4] = {0ull, 0ull, 0ull, 0ull};
    auto load = [&](int buf, int k0) {
        #pragma unroll
        for (int i = 0; i < 2; i++) {
            int id = tid*2 + i;
            int row = id >> 5, kk = id & 31;
            int sz = (row0 + row < rows) ? 4 : 0;
            CP4Z(smem_u32(&s.sA[buf][kk][row]), A + (size_t)(row0+row)*512 + k0 + kk, sz);
        }
        #pragma unroll
        for (int i = 0; i < 4; i++) {
            int id = tid + i*256;
            int kk = id >> 5, cq = (id & 31)*4;
            CP16(smem_u32(&s.sW[buf][kk][cq]), W + (size_t)(k0+kk)*512 + col0 + cq);
        }
        CP_COMMIT();
    };
    load(0, 0); load(1, 32);
    for (int st = 0; st < 16; st++) {
        int buf = st % 3;
        if (st + 2 < 16) { load((st+2)%3, (st+2)*32); CP_WAIT2(); }
        else if (st + 1 < 16) CP_WAIT1();
        else CP_WAIT0();
        __syncthreads();
        #pragma unroll
        for (int kk = 0; kk < 32; kk++) {
            u64 wv2 = dup2(s.sW[buf][kk][c]);
            #pragma unroll
            for (int p = 0; p < 4; p++) {
                u64 av = *(const u64*)&s.sA[buf][kk][rg*8 + 2*p];
                fma2(acc2[p], av, wv2);
            }
        }
        __syncthreads();
    }
    float bvv = bias ? bias[col0 + c] * bscale : 0.f;
    #pragma unroll
    for (int p = 0; p < 4; p++) {
        float lo, hi; un2(acc2[p], lo, hi);
        int r0 = row0 + rg*8 + 2*p;
        if (r0     < rows) C[(size_t)r0*512 + col0 + c]     = lo + bvv;
        if (r0 + 1 < rows) C[(size_t)(r0+1)*512 + col0 + c] = hi + bvv;
    }
}

// 16 rows x 64 cols, 3-buffer pipeline
__device__ void dev_gemm64(const float* __restrict__ A, const float* __restrict__ W,
                           const float* __restrict__ bias, float bscale,
                           float* __restrict__ C, int rows, int row0, int col0, Gemm64Sm& s) {
    int tid = threadIdx.x;
    int c = tid & 63, rg = tid >> 6;
    u64 acc2[2] = {0ull, 0ull};
    auto load = [&](int buf, int k0) {
        #pragma unroll
        for (int i = 0; i < 2; i++) {
            int id = tid*2 + i;
            int row = id >> 5, kk = id & 31;
            int sz = (row0 + row < rows) ? 4 : 0;
            CP4Z(smem_u32(&s.sA[buf][kk][row]), A + (size_t)(row0+row)*512 + k0 + kk, sz);
        }
        #pragma unroll
        for (int i = 0; i < 2; i++) {
            int id = tid + i*256;
            int kk = id >> 4, cq = (id & 15)*4;
            CP16(smem_u32(&s.sW[buf][kk][cq]), W + (size_t)(k0+kk)*512 + col0 + cq);
        }
        CP_COMMIT();
    };
    load(0, 0); load(1, 32);
    for (int st = 0; st < 16; st++) {
        int buf = st % 3;
        if (st + 2 < 16) { load((st+2)%3, (st+2)*32); CP_WAIT2(); }
        else if (st + 1 < 16) CP_WAIT1();
        else CP_WAIT0();
        __syncthreads();
        #pragma unroll
        for (int kk = 0; kk < 32; kk++) {
            u64 wv2 = dup2(s.sW[buf][kk][c]);
            #pragma unroll
            for (int p = 0; p < 2; p++) {
                u64 av = *(const u64*)&s.sA[buf][kk][rg*4 + 2*p];
                fma2(acc2[p], av, wv2);
            }
        }
        __syncthreads();
    }
    float bvv = bias ? bias[col0 + c] * bscale : 0.f;
    #pragma unroll
    for (int p = 0; p < 2; p++) {
        float lo, hi; un2(acc2[p], lo, hi);
        int r0 = row0 + rg*4 + 2*p;
        if (r0     < rows) C[(size_t)r0*512 + col0 + c]     = lo + bvv;
        if (r0 + 1 < rows) C[(size_t)(r0+1)*512 + col0 + c] = hi + bvv;
    }
}

// three 16x64 GEMMs sharing the W tile, 3-buffer pipeline
__device__ void dev_gemm3(const float* __restrict__ A0, const float* __restrict__ A1,
                          const float* __restrict__ A2, const float* __restrict__ W,
                          const float* __restrict__ bias,
                          float* __restrict__ C0, float* __restrict__ C1, float* __restrict__ C2,
                          int row0, int col0, Gemm3Sm& s) {
    int tid = threadIdx.x;
    int c = tid & 63, rg = tid >> 6;
    u64 acc2[3][2];
    #pragma unroll
    for (int q = 0; q < 3; q++) { acc2[q][0] = 0ull; acc2[q][1] = 0ull; }
    auto load = [&](int buf, int k0) {
        #pragma unroll
        for (int i = 0; i < 6; i++) {
            const int smat = i >> 1;
            int rem = tid + (i & 1)*256;
            int row = rem >> 5, kk = rem & 31;
            const float* Ap = (smat == 0) ? A0 : ((smat == 1) ? A1 : A2);
            CP4(smem_u32(&s.sA[buf][smat][kk][row]), Ap + (size_t)(row0+row)*512 + k0 + kk);
        }
        #pragma unroll
        for (int i = 0; i < 2; i++) {
            int id = tid + i*256;
            int kk = id >> 4, cq = (id & 15)*4;
            CP16(smem_u32(&s.sW[buf][kk][cq]), W + (size_t)(k0+kk)*512 + col0 + cq);
        }
        CP_COMMIT();
    };
    load(0, 0); load(1, 32);
    for (int st = 0; st < 16; st++) {
        int buf = st % 3;
        if (st + 2 < 16) { load((st+2)%3, (st+2)*32); CP_WAIT2(); }
        else if (st + 1 < 16) CP_WAIT1();
        else CP_WAIT0();
        __syncthreads();
        #pragma unroll
        for (int kk = 0; kk < 32; kk++) {
            u64 wv2 = dup2(s.sW[buf][kk][c]);
            #pragma unroll
            for (int p = 0; p < 2; p++) {
                fma2(acc2[0][p], *(const u64*)&s.sA[buf][0][kk][rg*4 + 2*p], wv2);
                fma2(acc2[1][p], *(const u64*)&s.sA[buf][1][kk][rg*4 + 2*p], wv2);
                fma2(acc2[2][p], *(const u64*)&s.sA[buf][2][kk][rg*4 + 2*p], wv2);
            }
        }
        __syncthreads();
    }
    float bvv = bias[col0 + c];
    #pragma unroll
    for (int p = 0; p < 2; p++) {
        int r0 = row0 + rg*4 + 2*p;
        float lo, hi;
        un2(acc2[0][p], lo, hi);
        C0[(size_t)r0*512 + col0 + c] = lo + bvv*(float)TT;
        C0[(size_t)(r0+1)*512 + col0 + c] = hi + bvv*(float)TT;
        un2(acc2[1][p], lo, hi);
        C1[(size_t)r0*512 + col0 + c] = lo + bvv;
        C1[(size_t)(r0+1)*512 + col0 + c] = hi + bvv;
        un2(acc2[2][p], lo, hi);
        C2[(size_t)r0*512 + col0 + c] = lo + bvv;
        C2[(size_t)(r0+1)*512 + col0 + c] = hi + bvv;
    }
}

__device__ void dev_pool(const float* __restrict__ S, const float* __restrict__ F,
                         const float* __restrict__ L, const float* __restrict__ conv_b,
                         const float* __restrict__ pool_w, const float* __restrict__ pool_b,
                         float* __restrict__ outp, int row0, int rows, PoolSm& s) {
    int tid = threadIdx.x;
    for (int i = tid; i < 4*CC; i += 256) {
        int rs = i >> 9, c = i & 511;
        int row = row0 + rs;
        float vs = 0.f, vf = 0.f, vl = 0.f;
        if (row < rows) { vs = S[row*CC+c]; vf = F[row*CC+c]; vl = L[row*CC+c]; }
        s.sS[rs][c] = vs; s.sF[rs][c] = vf; s.sL[rs][c] = vl;
    }
    __syncthreads();
    {
        int r = tid & 63, rs = tid >> 6;
        float aS = 0.f, aF = 0.f, aL = 0.f;
        #pragma unroll 8
        for (int c = 0; c < CC; c++) {
            aS += __ldg(&g_wsC[c*RR + r]) * s.sS[rs][c];
            aL += __ldg(&g_w0C[c*RR + r]) * s.sL[rs][c];
            aF += __ldg(&g_w2C[c*RR + r]) * s.sF[rs][c];
        }
        s.smc[rs][r] = (aS - aL - aF) * (1.0f/TT) + conv_b[r];
    }
    __syncthreads();
    int c = tid;
    float acc[4][2];
    #pragma unroll
    for (int rs = 0; rs < 4; rs++) { acc[rs][0] = 0.f; acc[rs][1] = 0.f; }
    #pragma unroll 8
    for (int r = 0; r < RR; r++) {
        float w0 = pool_w[r*CC + c];
        float w1 = pool_w[r*CC + c + 256];
        #pragma unroll
        for (int rs = 0; rs < 4; rs++) { acc[rs][0] += s.smc[rs][r]*w0; acc[rs][1] += s.smc[rs][r]*w1; }
    }
    #pragma unroll
    for (int rs = 0; rs < 4; rs++) {
        int row = row0 + rs;
        if (row < rows) {
            outp[row*CC + c]       = acc[rs][0] + pool_b[c];
            outp[row*CC + c + 256] = acc[rs][1] + pool_b[c+256];
        }
    }
    __syncthreads();
}

// coalesced weight -> bf16 hi/lo via 64x64 smem transpose
__device__ void dev_wprep(const float* __restrict__ Wsrc, int kt, int nt, int kofs, WprepSm& s) {
    int tid = threadIdx.x;
    #pragma unroll
    for (int i = 0; i < 16; i++) {
        int idx = tid + i*256;
        int kr = idx >> 6, nc = idx & 63;
        s.t[kr][nc] = Wsrc[(size_t)(kt+kr)*512 + nt + nc];
    }
    __syncthreads();
    #pragma unroll
    for (int i = 0; i < 16; i++) {
        int idx = tid + i*256;
        int nr = idx >> 6, kc = idx & 63;
        float w = s.t[kc][nr];
        __nv_bfloat16 h = __float2bfloat16(w);
        size_t o = (size_t)(nt+nr)*1024 + kofs + kt + kc;
        g_Bhi[o] = h;
        g_Blo[o] = __float2bfloat16(w - __bfloat162float(h));
    }
    __syncthreads();
}

// Z (bf16 hi/lo) tile; swc must already be loaded in s.swc
__device__ void dev_zmix_nosw(const float* __restrict__ protos, int t, int c0, ZmixSm& s) {
    int tid = threadIdx.x;
    for (int i = tid; i < MNP*128; i += 256) {
        int mn = i >> 7, c = i & 127;
        s.sP[mn][c] = protos[((size_t)(mn*TT) + t)*CC + c0 + c];
    }
    __syncthreads();
    int b = tid & 31, cslot = tid >> 5;
    int cb = cslot * 16;
    u64 acc[8];
    #pragma unroll
    for (int j = 0; j < 8; j++) acc[j] = 0ull;
    #pragma unroll 4
    for (int mn = 0; mn < MNP; mn++) {
        u64 wv = dup2(s.swc[b][mn]);
        #pragma unroll
        for (int j = 0; j < 8; j++) {
            u64 pv = *(const u64*)&s.sP[mn][cb + 2*j];
            fma2(acc[j], pv, wv);
        }
    }
    size_t ofs = (size_t)(b*TT + t)*CC + c0 + cb;
    __nv_bfloat162* zh = (__nv_bfloat162*)(g_Zhi + ofs);
    __nv_bfloat162* zl = (__nv_bfloat162*)(g_Zlo + ofs);
    #pragma unroll
    for (int j = 0; j < 8; j++) {
        float v0, v1; un2(acc[j], v0, v1);
        __nv_bfloat16 h0 = __float2bfloat16(v0);
        __nv_bfloat16 h1 = __float2bfloat16(v1);
        zh[j] = __halves2bfloat162(h0, h1);
        zl[j] = __halves2bfloat162(__float2bfloat16(v0 - __bfloat162float(h0)),
                                   __float2bfloat16(v1 - __bfloat162float(h1)));
    }
    __syncthreads();
}

// ---------------- final GEMM tile: 3-term split, operand-reuse ordering,
// 3-buf/operand, depth-2 prefetch, single __syncthreads per stage ----------------
__device__ void dev_final(int job, float* __restrict__ out, char* dsm) {
    uint32_t sAu = smem_u32(dsm);                     // A: [3][128][72]
    uint32_t sBu = sAu + 3*TILE_BYTES;                // B: [3][128][72]
    int tid = threadIdx.x;
    int wid = tid >> 5, lane = tid & 31;
    int wm = wid & 3, wn = wid >> 2;
    int row0 = (job >> 2) * 128;
    int col0 = (job & 3) * 128;

    __syncthreads();   // isolate smem reuse from previous phase/job

    float acc[2][8][4];
    #pragma unroll
    for (int i = 0; i < 2; i++)
        #pragma unroll
        for (int j = 0; j < 8; j++)
            #pragma unroll
            for (int q = 0; q < 4; q++) acc[i][j][q] = 0.f;

    auto loadA = [&](int buf, int s) {
        int kc = s / 3, phase = s - kc*3;
        const __nv_bfloat16* Ah = (phase == 2) ? ((kc < 8) ? g_Zlo : g_Xlo)
                                               : ((kc < 8) ? g_Zhi : g_Xhi);
        int acol = (kc & 7) * 64;
        uint32_t ab = sAu + buf*TILE_BYTES;
        #pragma unroll
        for (int i = 0; i < 4; i++) {
            int id = tid + i*256;
            int row = id >> 3, seg = id & 7;
            CP16(ab + (row*ASTRIDE + seg*8)*2, Ah + (size_t)(row0+row)*512 + acol + seg*8);
        }
    };
    auto loadB = [&](int buf, int s) {
        int kc = s / 3, phase = s - kc*3;
        const __nv_bfloat16* Bs = (phase == 0) ? g_Blo : g_Bhi;
        int bcol = kc * 64;
        uint32_t bb = sBu + buf*TILE_BYTES;
        #pragma unroll
        for (int i = 0; i < 4; i++) {
            int id = tid + i*256;
            int row = id >> 3, seg = id & 7;
            CP16(bb + (row*ASTRIDE + seg*8)*2, Bs + (size_t)(col0+row)*1024 + bcol + seg*8);
        }
    };

    int acnt = 0, bcnt = 0;
    int abuf = acnt % 3; loadA(abuf, 0); acnt++;
    int bbuf = bcnt % 3; loadB(bbuf, 0); bcnt++;
    CP_COMMIT();                                  // group for stage 0
    int abuf_n = abuf;                            // stage1 A unchanged
    int bbuf_n = bcnt % 3; loadB(bbuf_n, 1); bcnt++;
    CP_COMMIT();                                  // group for stage 1

    for (int s = 0; s < NSTAGE; s++) {
        CP_WAIT1();
        __syncthreads();
        int abuf_u = abuf_n, bbuf_u = bbuf_n;
        if (s + 2 < NSTAGE) {
            int ph = (s + 2) % 3;
            if (ph != 1) { abuf_u = acnt % 3; loadA(abuf_u, s + 2); acnt++; }
            if (ph != 2) { bbuf_u = bcnt % 3; loadB(bbuf_u, s + 2); bcnt++; }
        }
        CP_COMMIT();

        uint32_t ab = sAu + abuf*TILE_BYTES;
        uint32_t bb = sBu + bbuf*TILE_BYTES;
        int a_row = (lane & 15);
        int a_k8  = (lane >> 4) * 8;
        int b_n   = (lane & 7) + (lane >> 4) * 8;
        int b_k8  = ((lane >> 3) & 1) * 8;

        #pragma unroll
        for (int k16 = 0; k16 < 4; k16++) {
            int kof = k16 * 16;
            uint32_t a[2][4];
            #pragma unroll
            for (int mi = 0; mi < 2; mi++) {
                uint32_t addr = ab + ((wm*32 + mi*16 + a_row)*ASTRIDE + kof + a_k8)*2;
                ldm_x4(a[mi][0], a[mi][1], a[mi][2], a[mi][3], addr);
            }
            #pragma unroll
            for (int nj = 0; nj < 4; nj++) {
                uint32_t b[4];
                uint32_t addr = bb + ((wn*64 + nj*16 + b_n)*ASTRIDE + kof + b_k8)*2;
                ldm_x4(b[0], b[1], b[2], b[3], addr);
                #pragma unroll
                for (int mi = 0; mi < 2; mi++) {
                    mma_bf16(acc[mi][nj*2],     a[mi], &b[0]);
                    mma_bf16(acc[mi][nj*2 + 1], a[mi], &b[2]);
                }
            }
        }
        abuf = abuf_n; bbuf = bbuf_n;
        abuf_n = abuf_u; bbuf_n = bbuf_u;
    }

    float2* o2 = (float2*)out;
    #pragma unroll
    for (int mi = 0; mi < 2; mi++) {
        #pragma unroll
        for (int nj = 0; nj < 8; nj++) {
            int c = col0 + wn*64 + nj*8 + (lane & 3)*2;
            float bz0 = g_bz[c], bz1 = g_bz[c+1];
            int e = c >> 1;
            #pragma unroll
            for (int h = 0; h < 2; h++) {
                int m = row0 + wm*32 + mi*16 + (lane >> 2) + h*8;
                int b = m >> 9, t = m & 511;
                float v0 = acc[mi][nj][h*2]   + bz0;
                float v1 = acc[mi][nj][h*2+1] + bz1;
                o2[(size_t)(b*EE + e)*TT + t] = make_float2(v0, v1);
            }
        }
    }
    __syncthreads();
}

__global__ void __launch_bounds__(256, 2) fused_all(
    const float* __restrict__ x_ri,
    const float* __restrict__ protos,
    const unsigned char* __restrict__ masks,
    const float* __restrict__ conv_w,
    const float* __restrict__ conv_b, const float* __restrict__ pool_w, const float* __restrict__ pool_b,
    const float* __restrict__ ln_g, const float* __restrict__ ln_b,
    const float* __restrict__ wqp, const float* __restrict__ bqp,
    const float* __restrict__ wkp, const float* __restrict__ bkp,
    const float* __restrict__ wvp, const float* __restrict__ bvp,
    const float* __restrict__ wq,  const float* __restrict__ bq,
    const float* __restrict__ wk,  const float* __restrict__ bk,
    const float* __restrict__ wv,  const float* __restrict__ bv,
    const float* __restrict__ wy,  const float* __restrict__ by,
    float* __restrict__ out, float* __restrict__ aw2out) {
    extern __shared__ __align__(16) char dsm[];
    FusedSm& sm = *(FusedSm*)dsm;
    int tid = threadIdx.x;
    unsigned tgt = *(volatile unsigned*)&g_bargen + 1;

    // ---- P0: ln (1024) + proto-redt (640) + conv repack (128) + mask (1) = 1793
    for (int j = blockIdx.x; j < 1793; j += FG) {
        if (j < 1024) {
            dev_ln(x_ri, ln_g, ln_b, j >> 5, j & 31, sm.l);
        } else if (j < 1664) {
            int g = j - 1024;
            int row = g >> 4, seg = (g >> 1) & 7, ch = g & 1;
            int c = ch*256 + tid;
            const int tseg = TT/8;
            const float* p = protos + ((size_t)row*TT + seg*tseg)*CC + c;
            float a = 0.f;
            #pragma unroll 8
            for (int t = 0; t < tseg; t++) a += p[(size_t)t*CC];
            g_Pp[((size_t)row*8 + seg)*CC + c] = a;
            if (seg == 0) g_P0[row*CC + c] = p[0];
            if (seg == 7) g_PT[row*CC + c] = p[(size_t)(tseg-1)*CC];
        } else if (j < 1792) {
            int idx = (j - 1664)*256 + tid;
            int r = idx >> 9, c = idx & 511;
            const float* p = conv_w + (size_t)(r*CC + c)*3;
            float w0 = p[0], w1 = p[1], w2 = p[2];
            g_wsC[c*RR + r] = w0 + w1 + w2;
            g_w0C[c*RR + r] = w0;
            g_w2C[c*RR + r] = w2;
        } else {
            if (tid < MNP) {
                int i = tid;
                int mode = masks[5] ? 0 : (masks[3] ? 1 : 2);
                unsigned char v = (mode == 0) ? masks[i] : ((mode == 1) ? masks[4*i+3] : masks[4*i]);
                g_maskf[i] = v ? 1.0f : 0.0f;
            }
        }
    }
    gbar(tgt);

    // ---- P1: combines(72) + gemmW1 (128) + wprep2 wy (64) + vecmm1 (16) = 280
    for (int j = blockIdx.x; j < 280; j += FG) {
        if (j < 72) {
            if (j < BB) {
                for (int ci = tid; ci < CC; ci += 256) {
                    float a = 0.f;
                    #pragma unroll 8
                    for (int s2 = 0; s2 < 32; s2++) a += g_Sxp[(size_t)(j*32 + s2)*CC + ci];
                    g_Sx[j*CC + ci] = a;
                }
            } else {
                int row = j - BB;
                for (int ci = tid; ci < CC; ci += 256) {
                    float a = 0.f;
                    #pragma unroll
                    for (int s2 = 0; s2 < 8; s2++) a += g_Pp[(size_t)(row*8 + s2)*CC + ci];
                    g_Sp[row*CC + ci] = a;
                }
            }
        } else if (j < 200) {
            int g = j - 72;
            dev_gemm(wvp, wv, (const float*)0, 0.f, g_tmpW, 512, (g>>2)*16, (g&3)*128, sm.g);
        } else if (j < 264) {
            int g = j - 200;
            dev_wprep(wy, (g&7)*64, (g>>3)*64, 512, sm.w);
        } else {
            int v = j - 264; int cb = v & 3, rs = v >> 2;
            int c = cb*128 + (tid & 127), rh = tid >> 7;
            int rbase = rs*128 + rh*64;
            float a = 0.f;
            #pragma unroll 8
            for (int r = 0; r < 64; r++) a += __ldg(&bvp[rbase+r]) * wv[(size_t)(rbase+r)*512 + c];
            g_vp1[(rs*2+rh)*CC + c] = a;
        }
    }
    gbar(tgt);

    // ---- P2: pools(18) + gemmW2 (128) + bvw combine (1) = 147
    for (int j = blockIdx.x; j < 147; j += FG) {
        if (j < 18) {
            if (j < 8) dev_pool(g_Sx, g_X0, g_XT, conv_b, pool_w, pool_b, g_xq, j*4, BB, sm.p);
            else       dev_pool(g_Sp, g_P0, g_PT, conv_b, pool_w, pool_b, g_pk, (j-8)*4, MNP, sm.p);
        } else if (j < 146) {
            int g = j - 18;
            dev_gemm(g_tmpW, wy, (const float*)0, 0.f, g_Wz, 512, (g>>2)*16, (g&3)*128, sm.g);
        } else {
            for (int c = tid; c < CC; c += 256) {
                float a = bv[c];
                #pragma unroll
                for (int p = 0; p < 8; p++) a += g_vp1[p*CC + c];
                g_bvw[c] = a;
            }
        }
    }
    gbar(tgt);

    // ---- P3: qprot(16)+keysp(24)+q(16) + wprep Wz (64) + vecmm2 (16) = 136
    for (int j = blockIdx.x; j < 136; j += FG) {
        if (j < 16)        dev_gemm64(g_xq, wqp, bqp, 1.f, g_qprot, BB, (j>>3)*16, (j&7)*64, sm.g64);
        else if (j < 40) { int g = j-16; dev_gemm64(g_pk, wkp, bkp, 1.f, g_keysp, MNP, (g>>3)*16, (g&7)*64, sm.g64); }
        else if (j < 56) { int g = j-40; dev_gemm64(g_xq, wq, bq, 1.f, g_q, BB, (g>>3)*16, (g&7)*64, sm.g64); }
        else if (j < 120) {
            int g = j - 56;
            dev_wprep(g_Wz, (g&7)*64, (g>>3)*64, 0, sm.w);
        } else {
            int v = j - 120; int cb = v & 3, rs = v >> 2;
            int c = cb*128 + (tid & 127), rh = tid >> 7;
            int rbase = rs*128 + rh*64;
            float a = 0.f;
            #pragma unroll 8
            for (int r = 0; r < 64; r++) a += g_bvw[rbase+r] * wy[(size_t)(rbase+r)*512 + c];
            g_vp2[(rs*2+rh)*CC + c] = a;
        }
    }
    gbar(tgt);

    // ---- P4: aw1 raw dots + bz combine (block 0) ----
    if (blockIdx.x == 0) {
        for (int c = tid; c < CC; c += 256) {
            float a = by[c];
            #pragma unroll
            for (int p = 0; p < 8; p++) a += g_vp2[p*CC + c];
            g_bz[c] = a;
        }
    }
    {
        int wg = blockIdx.x*8 + (tid >> 5), lane = tid & 31;
        for (int d = wg; d < BB*MM*NN; d += FG*8) {
            int b = d / 40, r2 = d - b*40, m = r2 / 5, n = r2 - m*5;
            const float* q  = g_qprot + (size_t)b*CC;
            const float* kk = g_keysp + (size_t)(m*NN + n)*CC;
            float s = 0.f;
            for (int i = lane; i < CC; i += 32) s += q[i]*kk[i];
            #pragma unroll
            for (int o = 16; o; o >>= 1) s += __shfl_down_sync(0xffffffffu, s, o);
            if (lane == 0) g_aw1[(b*MM + m)*NN + n] = s * INV_SCALE;
        }
    }
    gbar(tgt);

    // ---- P5: mixred (256 one-bm jobs) + aw1s write (1) = 257 ----
    for (int j = blockIdx.x; j < 257; j += FG) {
        if (j < 256) {
            int bm = j; int m = bm & 7;
            float a1[NN];
            {
                float mx = -1e30f;
                #pragma unroll
                for (int n = 0; n < NN; n++) {
                    a1[n] = g_aw1[bm*NN + n];
                    if (g_maskf[m*NN + n] != 0.f) mx = fmaxf(mx, a1[n]);
                }
                float sum = 0.f;
                #pragma unroll
                for (int n = 0; n < NN; n++) {
                    a1[n] = (g_maskf[m*NN+n] != 0.f) ? __expf(a1[n]-mx) : 0.f;
                    sum += a1[n];
                }
                float inv = 1.f/sum;
                #pragma unroll
                for (int n = 0; n < NN; n++) a1[n] *= inv;
            }
            #pragma unroll
            for (int cq = 0; cq < 2; cq++) {
                int ci = tid + cq*256;
                float s = 0.f, f = 0.f, l = 0.f;
                #pragma unroll
                for (int n = 0; n < NN; n++) {
                    int off = (m*NN + n)*CC + ci;
                    s += a1[n]*g_Sp[off]; f += a1[n]*g_P0[off]; l += a1[n]*g_PT[off];
                }
                g_SPm[bm*CC+ci] = s; g_P0m[bm*CC+ci] = f; g_PTm[bm*CC+ci] = l;
            }
        } else {
            int bm = tid;
            int m = bm & 7;
            float a1[NN]; float mx = -1e30f;
            #pragma unroll
            for (int n = 0; n < NN; n++) {
                a1[n] = g_aw1[bm*NN + n];
                if (g_maskf[m*NN + n] != 0.f) mx = fmaxf(mx, a1[n]);
            }
            float sum = 0.f;
            #pragma unroll
            for (int n = 0; n < NN; n++) { a1[n] = (g_maskf[m*NN+n] != 0.f) ? __expf(a1[n]-mx) : 0.f; sum += a1[n]; }
            float inv = 1.f/sum;
            #pragma unroll
            for (int n = 0; n < NN; n++) g_aw1s[bm*NN + n] = a1[n]*inv;
        }
    }
    gbar(tgt);

    // ---- P6: fused-3 gemms Sy/Fy/Ly ----
    for (int j = blockIdx.x; j < 128; j += FG) {
        dev_gemm3(g_SPm, g_P0m, g_PTm, wvp, bvp, g_Sy, g_Fy, g_Ly,
                  (j>>3)*16, (j&7)*64, sm.g3);
    }
    gbar(tgt);

    // ---- P7: pool y ----
    for (int j = blockIdx.x; j < 64; j += FG)
        dev_pool(g_Sy, g_Fy, g_Ly, conv_b, pool_w, pool_b, g_yks, j*4, BB*MM, sm.p);
    gbar(tgt);

    // ---- P8: gemm k = yks@wk ----
    for (int j = blockIdx.x; j < 128; j += FG)
        dev_gemm64(g_yks, wk, bk, 1.f, g_k, BB*MM, (j>>3)*16, (j&7)*64, sm.g64);
    gbar(tgt);

    // ---- P9: aw2 dots ----
    {
        int wg = blockIdx.x*8 + (tid >> 5), lane = tid & 31;
        for (int d = wg; d < BB*MM; d += FG*8) {
            int b = d >> 3;
            const float* q  = g_q + (size_t)b*CC;
            const float* kk = g_k + (size_t)d*CC;
            float s = 0.f;
            for (int i = lane; i < CC; i += 32) s += q[i]*kk[i];
            #pragma unroll
            for (int o = 16; o; o >>= 1) s += __shfl_down_sync(0xffffffffu, s, o);
            if (lane == 0) g_sc2[d] = s * INV_SCALE;
        }
    }
    gbar(tgt);

    // ---- P10: aw2 softmax + wcoef + aw2 output ----
    if (blockIdx.x == 0 && tid < BB) {
        int b = tid;
        float mx = -1e30f;
        #pragma unroll
        for (int m = 0; m < MM; m++) mx = fmaxf(mx, g_sc2[b*MM + m]);
        float e[MM]; float sum = 0.f;
        #pragma unroll
        for (int m = 0; m < MM; m++) { e[m] = __expf(g_sc2[b*MM+m] - mx); sum += e[m]; }
        float inv = 1.f/sum;
        #pragma unroll
        for (int m = 0; m < MM; m++) {
            float a = e[m]*inv;
            aw2out[b*MM + m] = a;
            #pragma unroll
            for (int n = 0; n < NN; n++) g_wcoef[b*MNP + m*NN + n] = a * g_aw1s[(b*MM+m)*NN + n];
        }
    }
    gbar(tgt);

    // ---- P11: zmix (2048 jobs) — swc loaded once per block ----
    for (int i = tid; i < 32*MNP; i += 256) {
        int b = i / MNP, mn = i - b*MNP;
        sm.z.swc[b][mn] = g_wcoef[i];
    }
    __syncthreads();
    for (int j = blockIdx.x; j < 4*TT; j += FG)
        dev_zmix_nosw(protos, j >> 2, (j & 3)*128, sm.z);
    gbar(tgt);

    // ---- P12: final GEMM, 512 tiles, exactly 2 per block ----
    for (int j = blockIdx.x; j < 512; j += FG)
        dev_final(j, out, dsm);
}

extern "C" void kernel_launch(void* const* d_in, const int* in_sizes, int n_in,
                              void* d_out, int out_size) {
    const float* x_ri   = (const float*)d_in[0];
    const float* protos = (const float*)d_in[1];
    const unsigned char* masks = (const unsigned char*)d_in[2];
    const float* conv_w = (const float*)d_in[3];
    const float* conv_b = (const float*)d_in[4];
    const float* pool_w = (const float*)d_in[5];
    const float* pool_b = (const float*)d_in[6];
    const float* ln_g   = (const float*)d_in[7];
    const float* ln_b   = (const float*)d_in[8];
    const float* wqp = (const float*)d_in[9];  const float* bqp = (const float*)d_in[10];
    const float* wkp = (const float*)d_in[11]; const float* bkp = (const float*)d_in[12];
    const float* wvp = (const float*)d_in[13]; const float* bvp = (const float*)d_in[14];
    const float* wq  = (const float*)d_in[15]; const float* bq  = (const float*)d_in[16];
    const float* wk  = (const float*)d_in[17]; const float* bk  = (const float*)d_in[18];
    const float* wv  = (const float*)d_in[19]; const float* bv  = (const float*)d_in[20];
    const float* wy  = (const float*)d_in[21]; const float* by  = (const float*)d_in[22];
    float* out = (float*)d_out;

    cudaFuncSetAttribute(fused_all, cudaFuncAttributeMaxDynamicSharedMemorySize, DSM_BYTES);

    fused_all<<<FG, 256, DSM_BYTES>>>(x_ri, protos, masks, conv_w,
                                      conv_b, pool_w, pool_b, ln_g, ln_b,
                                      wqp, bqp, wkp, bkp, wvp, bvp,
                                      wq, bq, wk, bk, wv, bv, wy, by,
                                      out, out + (size_t)BB*EE*TT*2);
}

// round 17
// speedup vs baseline: 1.0461x; 1.0461x over previous
#include <cuda_runtime.h>
#include <cuda_bf16.h>
#include <cstdint>

#define BB 32
#define EE 256
#define TT 512
#define MM 8
#define NN 5
#define CC 512
#define RR 64
#define MNP 40
#define LN_EPS 1e-5f
#define INV_SCALE 0.044194173824159216f  /* 1/sqrt(512) */
#define FG 256   /* fused kernel grid (2 CTAs/SM, all co-resident) */

typedef unsigned long long u64;

__device__ __forceinline__ void fma2(u64& d, u64 a, u64 b){
    asm("fma.rn.f32x2 %0,%1,%2,%0;" : "+l"(d) : "l"(a), "l"(b));
}
__device__ __forceinline__ u64 dup2(float x){ u64 r; asm("mov.b64 %0,{%1,%1};":"=l"(r):"f"(x)); return r; }
__device__ __forceinline__ void un2(u64 v, float& lo, float& hi){ asm("mov.b64 {%0,%1},%2;":"=f"(lo),"=f"(hi):"l"(v)); }

__device__ __forceinline__ uint32_t smem_u32(const void* p) {
    uint32_t a;
    asm("{ .reg .u64 t; cvta.to.shared.u64 t, %1; cvt.u32.u64 %0, t; }" : "=r"(a) : "l"(p));
    return a;
}
#define CP16(dst, src) asm volatile("cp.async.cg.shared.global [%0], [%1], 16;" :: "r"(dst), "l"(src))
#define CP4(dst, src)  asm volatile("cp.async.ca.shared.global [%0], [%1], 4;" :: "r"(dst), "l"(src))
#define CP4Z(dst, src, sz) asm volatile("cp.async.ca.shared.global [%0], [%1], 4, %2;" :: "r"(dst), "l"(src), "r"(sz))
#define CP_COMMIT() asm volatile("cp.async.commit_group;" ::: "memory")
#define CP_WAIT2() asm volatile("cp.async.wait_group 2;" ::: "memory")
#define CP_WAIT1() asm volatile("cp.async.wait_group 1;" ::: "memory")
#define CP_WAIT0() asm volatile("cp.async.wait_group 0;" ::: "memory")

__device__ __forceinline__ void ldm_x4(uint32_t& r0, uint32_t& r1, uint32_t& r2, uint32_t& r3, uint32_t addr) {
    asm volatile("ldmatrix.sync.aligned.m8n8.x4.shared.b16 {%0,%1,%2,%3}, [%4];"
                 : "=r"(r0), "=r"(r1), "=r"(r2), "=r"(r3) : "r"(addr));
}
__device__ __forceinline__ void mma_bf16(float* d, const uint32_t* a, const uint32_t* b) {
    asm volatile("mma.sync.aligned.m16n8k16.row.col.f32.bf16.bf16.f32 "
                 "{%0,%1,%2,%3}, {%4,%5,%6,%7}, {%8,%9}, {%0,%1,%2,%3};"
                 : "+f"(d[0]), "+f"(d[1]), "+f"(d[2]), "+f"(d[3])
                 : "r"(a[0]), "r"(a[1]), "r"(a[2]), "r"(a[3]), "r"(b[0]), "r"(b[1]));
}

// ---------------- scratch (device globals; no allocation) ----------------
__device__ __nv_bfloat16 g_Zhi[BB*TT*CC], g_Zlo[BB*TT*CC];
__device__ __nv_bfloat16 g_Xhi[BB*TT*CC], g_Xlo[BB*TT*CC];
__device__ __nv_bfloat16 g_Bhi[CC*1024], g_Blo[CC*1024];
__device__ float g_Sxp[BB*32*CC];
__device__ float g_Pp[MNP*8*CC];
__device__ float g_Sx[BB*CC], g_X0[BB*CC], g_XT[BB*CC];
__device__ float g_Sp[MNP*CC], g_P0[MNP*CC], g_PT[MNP*CC];
__device__ float g_xq[BB*CC], g_pk[MNP*CC];
__device__ float g_qprot[BB*CC], g_keysp[MNP*CC], g_q[BB*CC];
__device__ float g_aw1[BB*MM*NN];      // RAW scaled dots (never overwritten)
__device__ float g_aw1s[BB*MM*NN];     // softmaxed
__device__ float g_SPm[BB*MM*CC], g_P0m[BB*MM*CC], g_PTm[BB*MM*CC];
__device__ float g_Sy[BB*MM*CC], g_Fy[BB*MM*CC], g_Ly[BB*MM*CC];
__device__ float g_yks[BB*MM*CC], g_k[BB*MM*CC];
__device__ float g_wcoef[BB*MNP];
__device__ __align__(256) float g_tmpW[CC*CC];
__device__ __align__(256) float g_Wz[CC*CC];
__device__ float g_bvw[CC], g_bz[CC];
__device__ float g_wsC[CC*RR], g_w0C[CC*RR], g_w2C[CC*RR];
__device__ float g_maskf[MNP];
__device__ float g_vp1[8*CC], g_vp2[8*CC];
__device__ float g_sc2[BB*MM];
__device__ unsigned g_leafc[32*32];    // padded leaf counters
__device__ unsigned g_rootc = 0, g_bargen = 0;

// ---------------- fused mid-pipeline smem ----------------
struct GemmSm  { float sA[3][32][18]; float sW[3][32][128]; };
struct Gemm64Sm{ float sA[3][32][18]; float sW[3][32][64]; };
struct Gemm3Sm { float sA[3][3][32][18]; float sW[3][32][64]; };
struct PoolSm  { float sS[4][CC]; float sF[4][CC]; float sL[4][CC]; float smc[4][RR]; };
struct WprepSm { float t[64][65]; };
struct ZmixSm  { float sP[2][MNP][128]; float swc[32][41]; };
struct LnSm    { float sx[EE][33]; float smu[16]; float srs[16]; };
union FusedSm { GemmSm g; Gemm64Sm g64; Gemm3Sm g3; PoolSm p; WprepSm w; ZmixSm z; LnSm l; };

__device__ __forceinline__ void gbar(unsigned& tgt) {
    __threadfence();
    __syncthreads();
    if (threadIdx.x == 0) {
        int leaf = blockIdx.x & 31;
        unsigned old = atomicInc(&g_leafc[leaf*32], FG/32 - 1);
        if (old == FG/32 - 1) {
            unsigned r = atomicInc(&g_rootc, 31);
            if (r == 31) atomicAdd(&g_bargen, 1);
        }
        while ((int)(*(volatile unsigned*)&g_bargen - tgt) < 0) __nanosleep(64);
    }
    tgt++;
    __syncthreads();
    __threadfence();
}

// ---------------- LayerNorm tile -> bf16 hi/lo + partial T-sums ----------------
__device__ void dev_ln(const float* __restrict__ x_ri,
                       const float* __restrict__ gam, const float* __restrict__ bet,
                       int b, int tblk, LnSm& s) {
    int t0 = tblk * 16;
    int tid = threadIdx.x;
    #pragma unroll
    for (int i = 0; i < 8; i++) {
        int id = tid + i*256;
        int e = id >> 3, q = id & 7;
        float4 v = *(const float4*)(x_ri + (size_t)(b*EE + e)*TT*2 + t0*2 + q*4);
        s.sx[e][q*4+0] = v.x; s.sx[e][q*4+1] = v.y; s.sx[e][q*4+2] = v.z; s.sx[e][q*4+3] = v.w;
    }
    __syncthreads();
    int w = tid >> 5, l = tid & 31;
    #pragma unroll
    for (int ttl = 0; ttl < 2; ttl++) {
        int tt = w*2 + ttl;
        float sv = 0.f, s2 = 0.f;
        #pragma unroll
        for (int i = 0; i < 8; i++) {
            int e = i*32 + l;
            float v0 = s.sx[e][tt*2], v1 = s.sx[e][tt*2+1];
            sv += v0 + v1; s2 += v0*v0 + v1*v1;
        }
        #pragma unroll
        for (int o = 16; o; o >>= 1) { sv += __shfl_down_sync(0xffffffffu, sv, o); s2 += __shfl_down_sync(0xffffffffu, s2, o); }
        if (l == 0) {
            float mu = sv * (1.f/CC);
            float var = s2 * (1.f/CC) - mu*mu;
            s.smu[tt] = mu; s.srs[tt] = rsqrtf(var + LN_EPS);
        }
    }
    __syncthreads();
    #pragma unroll
    for (int ci = 0; ci < 2; ci++) {
        int c = tid + ci*256;
        float gm = __ldg(&gam[c]), bt = __ldg(&bet[c]);
        int e = c >> 1, j = c & 1;
        float acc = 0.f;
        #pragma unroll
        for (int tt = 0; tt < 16; tt++) {
            float v = (s.sx[e][tt*2+j] - s.smu[tt]) * s.srs[tt] * gm + bt;
            acc += v;
            size_t row = (size_t)(b*TT + t0 + tt);
            __nv_bfloat16 h = __float2bfloat16(v);
            g_Xhi[row*CC + c] = h;
            g_Xlo[row*CC + c] = __float2bfloat16(v - __bfloat162float(h));
            if (tblk == 0 && tt == 0)  g_X0[b*CC + c] = v;
            if (tblk == 31 && tt == 15) g_XT[b*CC + c] = v;
        }
        g_Sxp[(size_t)(b*32 + tblk)*CC + c] = acc;
    }
    __syncthreads();
}

// 16 rows x 128 cols, 3-buffer cp.async pipeline, f32x2 accumulate
__device__ void dev_gemm(const float* __restrict__ A, const float* __restrict__ W,
                         const float* __restrict__ bias, float bscale,
                         float* __restrict__ C, int rows, int row0, int col0, GemmSm& s) {
    int tid = threadIdx.x;
    int c = tid & 127, rg = tid >> 7;
    u64 acc2[4] = {0ull, 0ull, 0ull, 0ull};
    auto load = [&](int buf, int k0) {
        #pragma unroll
        for (int i = 0; i < 2; i++) {
            int id = tid*2 + i;
            int row = id >> 5, kk = id & 31;
            int sz = (row0 + row < rows) ? 4 : 0;
            CP4Z(smem_u32(&s.sA[buf][kk][row]), A + (size_t)(row0+row)*512 + k0 + kk, sz);
        }
        #pragma unroll
        for (int i = 0; i < 4; i++) {
            int id = tid + i*256;
            int kk = id >> 5, cq = (id & 31)*4;
            CP16(smem_u32(&s.sW[buf][kk][cq]), W + (size_t)(k0+kk)*512 + col0 + cq);
        }
        CP_COMMIT();
    };
    load(0, 0); load(1, 32);
    for (int st = 0; st < 16; st++) {
        int buf = st % 3;
        if (st + 2 < 16) { load((st+2)%3, (st+2)*32); CP_WAIT2(); }
        else if (st + 1 < 16) CP_WAIT1();
        else CP_WAIT0();
        __syncthreads();
        #pragma unroll
        for (int kk = 0; kk < 32; kk++) {
            u64 wv2 = dup2(s.sW[buf][kk][c]);
            #pragma unroll
            for (int p = 0; p < 4; p++) {
                u64 av = *(const u64*)&s.sA[buf][kk][rg*8 + 2*p];
                fma2(acc2[p], av, wv2);
            }
        }
        __syncthreads();
    }
    float bvv = bias ? bias[col0 + c] * bscale : 0.f;
    #pragma unroll
    for (int p = 0; p < 4; p++) {
        float lo, hi; un2(acc2[p], lo, hi);
        int r0 = row0 + rg*8 + 2*p;
        if (r0     < rows) C[(size_t)r0*512 + col0 + c]     = lo + bvv;
        if (r0 + 1 < rows) C[(size_t)(r0+1)*512 + col0 + c] = hi + bvv;
    }
}

// 16 rows x 64 cols, 3-buffer pipeline
__device__ void dev_gemm64(const float* __restrict__ A, const float* __restrict__ W,
                           const float* __restrict__ bias, float bscale,
                           float* __restrict__ C, int rows, int row0, int col0, Gemm64Sm& s) {
    int tid = threadIdx.x;
    int c = tid & 63, rg = tid >> 6;
    u64 acc2[2] = {0ull, 0ull};
    auto load = [&](int buf, int k0) {
        #pragma unroll
        for (int i = 0; i < 2; i++) {
            int id = tid*2 + i;
            int row = id >> 5, kk = id & 31;
            int sz = (row0 + row < rows) ? 4 : 0;
            CP4Z(smem_u32(&s.sA[buf][kk][row]), A + (size_t)(row0+row)*512 + k0 + kk, sz);
        }
        #pragma unroll
        for (int i = 0; i < 2; i++) {
            int id = tid + i*256;
            int kk = id >> 4, cq = (id & 15)*4;
            CP16(smem_u32(&s.sW[buf][kk][cq]), W + (size_t)(k0+kk)*512 + col0 + cq);
        }
        CP_COMMIT();
    };
    load(0, 0); load(1, 32);
    for (int st = 0; st < 16; st++) {
        int buf = st % 3;
        if (st + 2 < 16) { load((st+2)%3, (st+2)*32); CP_WAIT2(); }
        else if (st + 1 < 16) CP_WAIT1();
        else CP_WAIT0();
        __syncthreads();
        #pragma unroll
        for (int kk = 0; kk < 32; kk++) {
            u64 wv2 = dup2(s.sW[buf][kk][c]);
            #pragma unroll
            for (int p = 0; p < 2; p++) {
                u64 av = *(const u64*)&s.sA[buf][kk][rg*4 + 2*p];
                fma2(acc2[p], av, wv2);
            }
        }
        __syncthreads();
    }
    float bvv = bias ? bias[col0 + c] * bscale : 0.f;
    #pragma unroll
    for (int p = 0; p < 2; p++) {
        float lo, hi; un2(acc2[p], lo, hi);
        int r0 = row0 + rg*4 + 2*p;
        if (r0     < rows) C[(size_t)r0*512 + col0 + c]     = lo + bvv;
        if (r0 + 1 < rows) C[(size_t)(r0+1)*512 + col0 + c] = hi + bvv;
    }
}

// three 16x64 GEMMs sharing the W tile, 3-buffer pipeline
__device__ void dev_gemm3(const float* __restrict__ A0, const float* __restrict__ A1,
                          const float* __restrict__ A2, const float* __restrict__ W,
                          const float* __restrict__ bias,
                          float* __restrict__ C0, float* __restrict__ C1, float* __restrict__ C2,
                          int row0, int col0, Gemm3Sm& s) {
    int tid = threadIdx.x;
    int c = tid & 63, rg = tid >> 6;
    u64 acc2[3][2];
    #pragma unroll
    for (int q = 0; q < 3; q++) { acc2[q][0] = 0ull; acc2[q][1] = 0ull; }
    auto load = [&](int buf, int k0) {
        #pragma unroll
        for (int i = 0; i < 6; i++) {
            const int smat = i >> 1;
            int rem = tid + (i & 1)*256;
            int row = rem >> 5, kk = rem & 31;
            const float* Ap = (smat == 0) ? A0 : ((smat == 1) ? A1 : A2);
            CP4(smem_u32(&s.sA[buf][smat][kk][row]), Ap + (size_t)(row0+row)*512 + k0 + kk);
        }
        #pragma unroll
        for (int i = 0; i < 2; i++) {
            int id = tid + i*256;
            int kk = id >> 4, cq = (id & 15)*4;
            CP16(smem_u32(&s.sW[buf][kk][cq]), W + (size_t)(k0+kk)*512 + col0 + cq);
        }
        CP_COMMIT();
    };
    load(0, 0); load(1, 32);
    for (int st = 0; st < 16; st++) {
        int buf = st % 3;
        if (st + 2 < 16) { load((st+2)%3, (st+2)*32); CP_WAIT2(); }
        else if (st + 1 < 16) CP_WAIT1();
        else CP_WAIT0();
        __syncthreads();
        #pragma unroll
        for (int kk = 0; kk < 32; kk++) {
            u64 wv2 = dup2(s.sW[buf][kk][c]);
            #pragma unroll
            for (int p = 0; p < 2; p++) {
                fma2(acc2[0][p], *(const u64*)&s.sA[buf][0][kk][rg*4 + 2*p], wv2);
                fma2(acc2[1][p], *(const u64*)&s.sA[buf][1][kk][rg*4 + 2*p], wv2);
                fma2(acc2[2][p], *(const u64*)&s.sA[buf][2][kk][rg*4 + 2*p], wv2);
            }
        }
        __syncthreads();
    }
    float bvv = bias[col0 + c];
    #pragma unroll
    for (int p = 0; p < 2; p++) {
        int r0 = row0 + rg*4 + 2*p;
        float lo, hi;
        un2(acc2[0][p], lo, hi);
        C0[(size_t)r0*512 + col0 + c] = lo + bvv*(float)TT;
        C0[(size_t)(r0+1)*512 + col0 + c] = hi + bvv*(float)TT;
        un2(acc2[1][p], lo, hi);
        C1[(size_t)r0*512 + col0 + c] = lo + bvv;
        C1[(size_t)(r0+1)*512 + col0 + c] = hi + bvv;
        un2(acc2[2][p], lo, hi);
        C2[(size_t)r0*512 + col0 + c] = lo + bvv;
        C2[(size_t)(r0+1)*512 + col0 + c] = hi + bvv;
    }
}

__device__ void dev_pool(const float* __restrict__ S, const float* __restrict__ F,
                         const float* __restrict__ L, const float* __restrict__ conv_b,
                         const float* __restrict__ pool_w, const float* __restrict__ pool_b,
                         float* __restrict__ outp, int row0, int rows, PoolSm& s) {
    int tid = threadIdx.x;
    for (int i = tid; i < 4*CC; i += 256) {
        int rs = i >> 9, c = i & 511;
        int row = row0 + rs;
        float vs = 0.f, vf = 0.f, vl = 0.f;
        if (row < rows) { vs = S[row*CC+c]; vf = F[row*CC+c]; vl = L[row*CC+c]; }
        s.sS[rs][c] = vs; s.sF[rs][c] = vf; s.sL[rs][c] = vl;
    }
    __syncthreads();
    {
        int r = tid & 63, rs = tid >> 6;
        float aS = 0.f, aF = 0.f, aL = 0.f;
        #pragma unroll 8
        for (int c = 0; c < CC; c++) {
            aS += __ldg(&g_wsC[c*RR + r]) * s.sS[rs][c];
            aL += __ldg(&g_w0C[c*RR + r]) * s.sL[rs][c];
            aF += __ldg(&g_w2C[c*RR + r]) * s.sF[rs][c];
        }
        s.smc[rs][r] = (aS - aL - aF) * (1.0f/TT) + conv_b[r];
    }
    __syncthreads();
    int c = tid;
    float acc[4][2];
    #pragma unroll
    for (int rs = 0; rs < 4; rs++) { acc[rs][0] = 0.f; acc[rs][1] = 0.f; }
    #pragma unroll 8
    for (int r = 0; r < RR; r++) {
        float w0 = pool_w[r*CC + c];
        float w1 = pool_w[r*CC + c + 256];
        #pragma unroll
        for (int rs = 0; rs < 4; rs++) { acc[rs][0] += s.smc[rs][r]*w0; acc[rs][1] += s.smc[rs][r]*w1; }
    }
    #pragma unroll
    for (int rs = 0; rs < 4; rs++) {
        int row = row0 + rs;
        if (row < rows) {
            outp[row*CC + c]       = acc[rs][0] + pool_b[c];
            outp[row*CC + c + 256] = acc[rs][1] + pool_b[c+256];
        }
    }
    __syncthreads();
}

// coalesced weight -> bf16 hi/lo via 64x64 smem transpose
__device__ void dev_wprep(const float* __restrict__ Wsrc, int kt, int nt, int kofs, WprepSm& s) {
    int tid = threadIdx.x;
    #pragma unroll
    for (int i = 0; i < 16; i++) {
        int idx = tid + i*256;
        int kr = idx >> 6, nc = idx & 63;
        s.t[kr][nc] = Wsrc[(size_t)(kt+kr)*512 + nt + nc];
    }
    __syncthreads();
    #pragma unroll
    for (int i = 0; i < 16; i++) {
        int idx = tid + i*256;
        int nr = idx >> 6, kc = idx & 63;
        float w = s.t[kc][nr];
        __nv_bfloat16 h = __float2bfloat16(w);
        size_t o = (size_t)(nt+nr)*1024 + kofs + kt + kc;
        g_Bhi[o] = h;
        g_Blo[o] = __float2bfloat16(w - __bfloat162float(h));
    }
    __syncthreads();
}

__global__ void __launch_bounds__(256, 2) fused_small(
    const float* __restrict__ x_ri,
    const float* __restrict__ protos,
    const unsigned char* __restrict__ masks,
    const float* __restrict__ conv_w,
    const float* __restrict__ conv_b, const float* __restrict__ pool_w, const float* __restrict__ pool_b,
    const float* __restrict__ ln_g, const float* __restrict__ ln_b,
    const float* __restrict__ wqp, const float* __restrict__ bqp,
    const float* __restrict__ wkp, const float* __restrict__ bkp,
    const float* __restrict__ wvp, const float* __restrict__ bvp,
    const float* __restrict__ wq,  const float* __restrict__ bq,
    const float* __restrict__ wk,  const float* __restrict__ bk,
    const float* __restrict__ wv,  const float* __restrict__ bv,
    const float* __restrict__ wy,  const float* __restrict__ by,
    float* __restrict__ aw2out) {
    __shared__ __align__(16) FusedSm sm;
    int tid = threadIdx.x;
    unsigned tgt = *(volatile unsigned*)&g_bargen + 1;

    // ---- P0: ln (1024) + proto-redt (640) + conv repack (128) + mask (1) = 1793
    for (int j = blockIdx.x; j < 1793; j += FG) {
        if (j < 1024) {
            dev_ln(x_ri, ln_g, ln_b, j >> 5, j & 31, sm.l);
        } else if (j < 1664) {
            int g = j - 1024;
            int row = g >> 4, seg = (g >> 1) & 7, ch = g & 1;
            int c = ch*256 + tid;
            const int tseg = TT/8;
            const float* p = protos + ((size_t)row*TT + seg*tseg)*CC + c;
            float a = 0.f;
            #pragma unroll 8
            for (int t = 0; t < tseg; t++) a += p[(size_t)t*CC];
            g_Pp[((size_t)row*8 + seg)*CC + c] = a;
            if (seg == 0) g_P0[row*CC + c] = p[0];
            if (seg == 7) g_PT[row*CC + c] = p[(size_t)(tseg-1)*CC];
        } else if (j < 1792) {
            int idx = (j - 1664)*256 + tid;
            int r = idx >> 9, c = idx & 511;
            const float* p = conv_w + (size_t)(r*CC + c)*3;
            float w0 = p[0], w1 = p[1], w2 = p[2];
            g_wsC[c*RR + r] = w0 + w1 + w2;
            g_w0C[c*RR + r] = w0;
            g_w2C[c*RR + r] = w2;
        } else {
            if (tid < MNP) {
                int i = tid;
                int mode = masks[5] ? 0 : (masks[3] ? 1 : 2);
                unsigned char v = (mode == 0) ? masks[i] : ((mode == 1) ? masks[4*i+3] : masks[4*i]);
                g_maskf[i] = v ? 1.0f : 0.0f;
            }
        }
    }
    gbar(tgt);

    // ---- P1: combines(72) + gemmW1 (128) + wprep2 wy (64) + vecmm1 (16) = 280
    for (int j = blockIdx.x; j < 280; j += FG) {
        if (j < 72) {
            if (j < BB) {
                for (int ci = tid; ci < CC; ci += 256) {
                    float a = 0.f;
                    #pragma unroll 8
                    for (int s2 = 0; s2 < 32; s2++) a += g_Sxp[(size_t)(j*32 + s2)*CC + ci];
                    g_Sx[j*CC + ci] = a;
                }
            } else {
                int row = j - BB;
                for (int ci = tid; ci < CC; ci += 256) {
                    float a = 0.f;
                    #pragma unroll
                    for (int s2 = 0; s2 < 8; s2++) a += g_Pp[(size_t)(row*8 + s2)*CC + ci];
                    g_Sp[row*CC + ci] = a;
                }
            }
        } else if (j < 200) {
            int g = j - 72;
            dev_gemm(wvp, wv, (const float*)0, 0.f, g_tmpW, 512, (g>>2)*16, (g&3)*128, sm.g);
        } else if (j < 264) {
            int g = j - 200;
            dev_wprep(wy, (g&7)*64, (g>>3)*64, 512, sm.w);
        } else {
            int v = j - 264; int cb = v & 3, rs = v >> 2;
            int c = cb*128 + (tid & 127), rh = tid >> 7;
            int rbase = rs*128 + rh*64;
            float a = 0.f;
            #pragma unroll 8
            for (int r = 0; r < 64; r++) a += __ldg(&bvp[rbase+r]) * wv[(size_t)(rbase+r)*512 + c];
            g_vp1[(rs*2+rh)*CC + c] = a;
        }
    }
    gbar(tgt);

    // ---- P2: pools(18) + gemmW2 (128) + bvw combine (1) = 147
    for (int j = blockIdx.x; j < 147; j += FG) {
        if (j < 18) {
            if (j < 8) dev_pool(g_Sx, g_X0, g_XT, conv_b, pool_w, pool_b, g_xq, j*4, BB, sm.p);
            else       dev_pool(g_Sp, g_P0, g_PT, conv_b, pool_w, pool_b, g_pk, (j-8)*4, MNP, sm.p);
        } else if (j < 146) {
            int g = j - 18;
            dev_gemm(g_tmpW, wy, (const float*)0, 0.f, g_Wz, 512, (g>>2)*16, (g&3)*128, sm.g);
        } else {
            for (int c = tid; c < CC; c += 256) {
                float a = bv[c];
                #pragma unroll
                for (int p = 0; p < 8; p++) a += g_vp1[p*CC + c];
                g_bvw[c] = a;
            }
        }
    }
    gbar(tgt);

    // ---- P3: qprot(16)+keysp(24)+q(16) + wprep Wz (64) + vecmm2 (16) = 136
    for (int j = blockIdx.x; j < 136; j += FG) {
        if (j < 16)        dev_gemm64(g_xq, wqp, bqp, 1.f, g_qprot, BB, (j>>3)*16, (j&7)*64, sm.g64);
        else if (j < 40) { int g = j-16; dev_gemm64(g_pk, wkp, bkp, 1.f, g_keysp, MNP, (g>>3)*16, (g&7)*64, sm.g64); }
        else if (j < 56) { int g = j-40; dev_gemm64(g_xq, wq, bq, 1.f, g_q, BB, (g>>3)*16, (g&7)*64, sm.g64); }
        else if (j < 120) {
            int g = j - 56;
            dev_wprep(g_Wz, (g&7)*64, (g>>3)*64, 0, sm.w);
        } else {
            int v = j - 120; int cb = v & 3, rs = v >> 2;
            int c = cb*128 + (tid & 127), rh = tid >> 7;
            int rbase = rs*128 + rh*64;
            float a = 0.f;
            #pragma unroll 8
            for (int r = 0; r < 64; r++) a += g_bvw[rbase+r] * wy[(size_t)(rbase+r)*512 + c];
            g_vp2[(rs*2+rh)*CC + c] = a;
        }
    }
    gbar(tgt);

    // ---- P4: aw1 raw dots + bz combine (block 0) ----
    if (blockIdx.x == 0) {
        for (int c = tid; c < CC; c += 256) {
            float a = by[c];
            #pragma unroll
            for (int p = 0; p < 8; p++) a += g_vp2[p*CC + c];
            g_bz[c] = a;
        }
    }
    {
        int wg = blockIdx.x*8 + (tid >> 5), lane = tid & 31;
        for (int d = wg; d < BB*MM*NN; d += FG*8) {
            int b = d / 40, r2 = d - b*40, m = r2 / 5, n = r2 - m*5;
            const float* q  = g_qprot + (size_t)b*CC;
            const float* kk = g_keysp + (size_t)(m*NN + n)*CC;
            float s = 0.f;
            for (int i = lane; i < CC; i += 32) s += q[i]*kk[i];
            #pragma unroll
            for (int o = 16; o; o >>= 1) s += __shfl_down_sync(0xffffffffu, s, o);
            if (lane == 0) g_aw1[(b*MM + m)*NN + n] = s * INV_SCALE;
        }
    }
    gbar(tgt);

    // ---- P5: mixred (256 one-bm jobs) + aw1s write (1) = 257 ----
    for (int j = blockIdx.x; j < 257; j += FG) {
        if (j < 256) {
            int bm = j; int m = bm & 7;
            float a1[NN];
            {
                float mx = -1e30f;
                #pragma unroll
                for (int n = 0; n < NN; n++) {
                    a1[n] = g_aw1[bm*NN + n];
                    if (g_maskf[m*NN + n] != 0.f) mx = fmaxf(mx, a1[n]);
                }
                float sum = 0.f;
                #pragma unroll
                for (int n = 0; n < NN; n++) {
                    a1[n] = (g_maskf[m*NN+n] != 0.f) ? __expf(a1[n]-mx) : 0.f;
                    sum += a1[n];
                }
                float inv = 1.f/sum;
                #pragma unroll
                for (int n = 0; n < NN; n++) a1[n] *= inv;
            }
            #pragma unroll
            for (int cq = 0; cq < 2; cq++) {
                int ci = tid + cq*256;
                float s = 0.f, f = 0.f, l = 0.f;
                #pragma unroll
                for (int n = 0; n < NN; n++) {
                    int off = (m*NN + n)*CC + ci;
                    s += a1[n]*g_Sp[off]; f += a1[n]*g_P0[off]; l += a1[n]*g_PT[off];
                }
                g_SPm[bm*CC+ci] = s; g_P0m[bm*CC+ci] = f; g_PTm[bm*CC+ci] = l;
            }
        } else {
            int bm = tid;
            int m = bm & 7;
            float a1[NN]; float mx = -1e30f;
            #pragma unroll
            for (int n = 0; n < NN; n++) {
                a1[n] = g_aw1[bm*NN + n];
                if (g_maskf[m*NN + n] != 0.f) mx = fmaxf(mx, a1[n]);
            }
            float sum = 0.f;
            #pragma unroll
            for (int n = 0; n < NN; n++) { a1[n] = (g_maskf[m*NN+n] != 0.f) ? __expf(a1[n]-mx) : 0.f; sum += a1[n]; }
            float inv = 1.f/sum;
            #pragma unroll
            for (int n = 0; n < NN; n++) g_aw1s[bm*NN + n] = a1[n]*inv;
        }
    }
    gbar(tgt);

    // ---- P6: fused-3 gemms Sy/Fy/Ly ----
    for (int j = blockIdx.x; j < 128; j += FG) {
        dev_gemm3(g_SPm, g_P0m, g_PTm, wvp, bvp, g_Sy, g_Fy, g_Ly,
                  (j>>3)*16, (j&7)*64, sm.g3);
    }
    gbar(tgt);

    // ---- P7: pool y ----
    for (int j = blockIdx.x; j < 64; j += FG)
        dev_pool(g_Sy, g_Fy, g_Ly, conv_b, pool_w, pool_b, g_yks, j*4, BB*MM, sm.p);
    gbar(tgt);

    // ---- P8: gemm k = yks@wk ----
    for (int j = blockIdx.x; j < 128; j += FG)
        dev_gemm64(g_yks, wk, bk, 1.f, g_k, BB*MM, (j>>3)*16, (j&7)*64, sm.g64);
    gbar(tgt);

    // ---- P9: aw2 dots ----
    {
        int wg = blockIdx.x*8 + (tid >> 5), lane = tid & 31;
        for (int d = wg; d < BB*MM; d += FG*8) {
            int b = d >> 3;
            const float* q  = g_q + (size_t)b*CC;
            const float* kk = g_k + (size_t)d*CC;
            float s = 0.f;
            for (int i = lane; i < CC; i += 32) s += q[i]*kk[i];
            #pragma unroll
            for (int o = 16; o; o >>= 1) s += __shfl_down_sync(0xffffffffu, s, o);
            if (lane == 0) g_sc2[d] = s * INV_SCALE;
        }
    }
    gbar(tgt);

    // ---- P10: aw2 softmax + wcoef + aw2 output ----
    if (blockIdx.x == 0 && tid < BB) {
        int b = tid;
        float mx = -1e30f;
        #pragma unroll
        for (int m = 0; m < MM; m++) mx = fmaxf(mx, g_sc2[b*MM + m]);
        float e[MM]; float sum = 0.f;
        #pragma unroll
        for (int m = 0; m < MM; m++) { e[m] = __expf(g_sc2[b*MM+m] - mx); sum += e[m]; }
        float inv = 1.f/sum;
        #pragma unroll
        for (int m = 0; m < MM; m++) {
            float a = e[m]*inv;
            aw2out[b*MM + m] = a;
            #pragma unroll
            for (int n = 0; n < NN; n++) g_wcoef[b*MNP + m*NN + n] = a * g_aw1s[(b*MM+m)*NN + n];
        }
    }
    gbar(tgt);

    // ---- P11: zmix (2048 jobs, 8 per block) — cp.async double-buffered protos tile ----
    for (int i = tid; i < 32*MNP; i += 256) {
        int b = i / MNP, mn = i - b*MNP;
        sm.z.swc[b][mn] = g_wcoef[i];
    }
    __syncthreads();
    {
        auto zload = [&](int buf, int j) {
            int t = j >> 2, c0 = (j & 3)*128;
            #pragma unroll
            for (int i = 0; i < 5; i++) {
                int id = tid + i*256;            // 0..1279: 40 rows x 32 chunks of 16B
                int mn = id >> 5, seg = id & 31;
                CP16(smem_u32(&sm.z.sP[buf][mn][seg*4]),
                     protos + ((size_t)(mn*TT) + t)*CC + c0 + seg*4);
            }
            CP_COMMIT();
        };
        zload(0, blockIdx.x);
        for (int k = 0; k < 8; k++) {
            int j = blockIdx.x + k*FG;
            int buf = k & 1;
            CP_WAIT0();
            __syncthreads();
            if (k + 1 < 8) zload(buf ^ 1, j + FG);
            // compute from sP[buf]
            int b = tid & 31, cslot = tid >> 5;
            int cb = cslot * 16;
            u64 acc[8];
            #pragma unroll
            for (int q = 0; q < 8; q++) acc[q] = 0ull;
            #pragma unroll 4
            for (int mn = 0; mn < MNP; mn++) {
                u64 wv = dup2(sm.z.swc[b][mn]);
                #pragma unroll
                for (int q = 0; q < 8; q++) {
                    u64 pv = *(const u64*)&sm.z.sP[buf][mn][cb + 2*q];
                    fma2(acc[q], pv, wv);
                }
            }
            int t = j >> 2, c0 = (j & 3)*128;
            size_t ofs = (size_t)(b*TT + t)*CC + c0 + cb;
            __nv_bfloat162* zh = (__nv_bfloat162*)(g_Zhi + ofs);
            __nv_bfloat162* zl = (__nv_bfloat162*)(g_Zlo + ofs);
            #pragma unroll
            for (int q = 0; q < 8; q++) {
                float v0, v1; un2(acc[q], v0, v1);
                __nv_bfloat16 h0 = __float2bfloat16(v0);
                __nv_bfloat16 h1 = __float2bfloat16(v1);
                zh[q] = __halves2bfloat162(h0, h1);
                zl[q] = __halves2bfloat162(__float2bfloat16(v0 - __bfloat162float(h0)),
                                           __float2bfloat16(v1 - __bfloat162float(h1)));
            }
        }
    }
}

// ---------------- final GEMM: 3-term split, operand-reuse ordering, 3-buf/operand,
// depth-2 prefetch, single __syncthreads per stage ----------------
#define ASTRIDE 72
#define TILE_BYTES (128*ASTRIDE*2)
#define NSTAGE 48

__global__ void __launch_bounds__(256, 2) final_mma(float* __restrict__ out) {
    extern __shared__ __nv_bfloat16 smx[];
    uint32_t sAu = smem_u32(smx);                         // A: [3][128][72]
    uint32_t sBu = smem_u32(smx + 3*128*ASTRIDE);         // B: [3][128][72]

    int tid = threadIdx.x;
    int wid = tid >> 5, lane = tid & 31;
    int wm = wid & 3, wn = wid >> 2;
    int row0 = blockIdx.y * 128;
    int col0 = blockIdx.x * 128;

    float acc[2][8][4];
    #pragma unroll
    for (int i = 0; i < 2; i++)
        #pragma unroll
        for (int j = 0; j < 8; j++)
            #pragma unroll
            for (int q = 0; q < 4; q++) acc[i][j][q] = 0.f;

    auto loadA = [&](int buf, int s) {
        int kc = s / 3, phase = s - kc*3;
        const __nv_bfloat16* Ah = (phase == 2) ? ((kc < 8) ? g_Zlo : g_Xlo)
                                               : ((kc < 8) ? g_Zhi : g_Xhi);
        int acol = (kc & 7) * 64;
        uint32_t ab = sAu + buf*TILE_BYTES;
        #pragma unroll
        for (int i = 0; i < 4; i++) {
            int id = tid + i*256;
            int row = id >> 3, seg = id & 7;
            CP16(ab + (row*ASTRIDE + seg*8)*2, Ah + (size_t)(row0+row)*512 + acol + seg*8);
        }
    };
    auto loadB = [&](int buf, int s) {
        int kc = s / 3, phase = s - kc*3;
        const __nv_bfloat16* Bs = (phase == 0) ? g_Blo : g_Bhi;
        int bcol = kc * 64;
        uint32_t bb = sBu + buf*TILE_BYTES;
        #pragma unroll
        for (int i = 0; i < 4; i++) {
            int id = tid + i*256;
            int row = id >> 3, seg = id & 7;
            CP16(bb + (row*ASTRIDE + seg*8)*2, Bs + (size_t)(col0+row)*1024 + bcol + seg*8);
        }
    };

    int acnt = 0, bcnt = 0;
    int abuf = acnt % 3; loadA(abuf, 0); acnt++;
    int bbuf = bcnt % 3; loadB(bbuf, 0); bcnt++;
    CP_COMMIT();                                  // group for stage 0
    int abuf_n = abuf;                            // stage1 A unchanged
    int bbuf_n = bcnt % 3; loadB(bbuf_n, 1); bcnt++;
    CP_COMMIT();                                  // group for stage 1

    for (int s = 0; s < NSTAGE; s++) {
        CP_WAIT1();
        __syncthreads();
        int abuf_u = abuf_n, bbuf_u = bbuf_n;
        if (s + 2 < NSTAGE) {
            int ph = (s + 2) % 3;
            if (ph != 1) { abuf_u = acnt % 3; loadA(abuf_u, s + 2); acnt++; }
            if (ph != 2) { bbuf_u = bcnt % 3; loadB(bbuf_u, s + 2); bcnt++; }
        }
        CP_COMMIT();

        uint32_t ab = sAu + abuf*TILE_BYTES;
        uint32_t bb = sBu + bbuf*TILE_BYTES;
        int a_row = (lane & 15);
        int a_k8  = (lane >> 4) * 8;
        int b_n   = (lane & 7) + (lane >> 4) * 8;
        int b_k8  = ((lane >> 3) & 1) * 8;

        #pragma unroll
        for (int k16 = 0; k16 < 4; k16++) {
            int kof = k16 * 16;
            uint32_t a[2][4];
            #pragma unroll
            for (int mi = 0; mi < 2; mi++) {
                uint32_t addr = ab + ((wm*32 + mi*16 + a_row)*ASTRIDE + kof + a_k8)*2;
                ldm_x4(a[mi][0], a[mi][1], a[mi][2], a[mi][3], addr);
            }
            #pragma unroll
            for (int nj = 0; nj < 4; nj++) {
                uint32_t b[4];
                uint32_t addr = bb + ((wn*64 + nj*16 + b_n)*ASTRIDE + kof + b_k8)*2;
                ldm_x4(b[0], b[1], b[2], b[3], addr);
                #pragma unroll
                for (int mi = 0; mi < 2; mi++) {
                    mma_bf16(acc[mi][nj*2],     a[mi], &b[0]);
                    mma_bf16(acc[mi][nj*2 + 1], a[mi], &b[2]);
                }
            }
        }
        abuf = abuf_n; bbuf = bbuf_n;
        abuf_n = abuf_u; bbuf_n = bbuf_u;
    }

    float2* o2 = (float2*)out;
    #pragma unroll
    for (int mi = 0; mi < 2; mi++) {
        #pragma unroll
        for (int nj = 0; nj < 8; nj++) {
            int c = col0 + wn*64 + nj*8 + (lane & 3)*2;
            float bz0 = g_bz[c], bz1 = g_bz[c+1];
            int e = c >> 1;
            #pragma unroll
            for (int h = 0; h < 2; h++) {
                int m = row0 + wm*32 + mi*16 + (lane >> 2) + h*8;
                int b = m >> 9, t = m & 511;
                float v0 = acc[mi][nj][h*2]   + bz0;
                float v1 = acc[mi][nj][h*2+1] + bz1;
                o2[(size_t)(b*EE + e)*TT + t] = make_float2(v0, v1);
            }
        }
    }
}

extern "C" void kernel_launch(void* const* d_in, const int* in_sizes, int n_in,
                              void* d_out, int out_size) {
    const float* x_ri   = (const float*)d_in[0];
    const float* protos = (const float*)d_in[1];
    const unsigned char* masks = (const unsigned char*)d_in[2];
    const float* conv_w = (const float*)d_in[3];
    const float* conv_b = (const float*)d_in[4];
    const float* pool_w = (const float*)d_in[5];
    const float* pool_b = (const float*)d_in[6];
    const float* ln_g   = (const float*)d_in[7];
    const float* ln_b   = (const float*)d_in[8];
    const float* wqp = (const float*)d_in[9];  const float* bqp = (const float*)d_in[10];
    const float* wkp = (const float*)d_in[11]; const float* bkp = (const float*)d_in[12];
    const float* wvp = (const float*)d_in[13]; const float* bvp = (const float*)d_in[14];
    const float* wq  = (const float*)d_in[15]; const float* bq  = (const float*)d_in[16];
    const float* wk  = (const float*)d_in[17]; const float* bk  = (const float*)d_in[18];
    const float* wv  = (const float*)d_in[19]; const float* bv  = (const float*)d_in[20];
    const float* wy  = (const float*)d_in[21]; const float* by  = (const float*)d_in[22];
    float* out = (float*)d_out;

    cudaFuncSetAttribute(final_mma, cudaFuncAttributeMaxDynamicSharedMemorySize, 6*TILE_BYTES);

    fused_small<<<FG, 256>>>(x_ri, protos, masks, conv_w,
                             conv_b, pool_w, pool_b, ln_g, ln_b,
                             wqp, bqp, wkp, bkp, wvp, bvp,
                             wq, bq, wk, bk, wv, bv, wy, by,
                             out + (size_t)BB*EE*TT*2);
    final_mma<<<dim3(512/128, BB*TT/128), 256, 6*TILE_BYTES>>>(out);
}